// round 11
// baseline (speedup 1.0000x reference)
#include <cuda_runtime.h>

#define B_TOT   16384
#define TM      32
#define NTHR    384
#define NSTEPS_ 10

typedef unsigned long long u64;

__device__ __forceinline__ u64 pk2(float lo, float hi) {
    u64 r; asm("mov.b64 %0,{%1,%2};" : "=l"(r) : "f"(lo), "f"(hi)); return r;
}
__device__ __forceinline__ float2 upk2(u64 v) {
    float2 f; asm("mov.b64 {%0,%1},%2;" : "=f"(f.x), "=f"(f.y) : "l"(v)); return f;
}
__device__ __forceinline__ void fma2(u64& d, u64 a, u64 b) {
    asm("fma.rn.f32x2 %0,%1,%2,%0;" : "+l"(d) : "l"(a), "l"(b));
}
__device__ __forceinline__ void add2(u64& d, u64 a) {
    asm("add.rn.f32x2 %0,%0,%1;" : "+l"(d) : "l"(a));
}

// Shared layout (floats):
//   [0,36864)      W2s   192x192
//   [36864,49920)  shA   192x68 act rows [a32|d32|pad4]
//                        (aliased: hS 256x32 prologue; a2t 32x196 + FJ3 at +8192)
//   [49920,52992)  shW3t 16x192
//   [52992,53008)  shB3  16
//   [53008,54096)  shYE  16x68  [y32|e32|pad4]
//   [54096,55632)  shFB  3x512
//   [55632,56144)  shY   32x16
//   [56144,56176)  shTR  32
//   [56176,56272)  shTW  12x8 warp trace partials
#define SMEM_FLOATS 56272

__global__ __launch_bounds__(NTHR, 1)
void ConditionalCNF_27590869910221_kernel(
    const float* __restrict__ theta, const float* __restrict__ hg,
    const float* __restrict__ eps,   const float* __restrict__ W1,
    const float* __restrict__ b1,    const float* __restrict__ W2,
    const float* __restrict__ b2,    const float* __restrict__ W3,
    const float* __restrict__ b3,    float* __restrict__ out)
{
    extern __shared__ float sm[];
    float* shW2  = sm;
    float* shA   = sm + 36864;
    float* shW3t = sm + 49920;
    float* shB3  = sm + 52992;
    float* shYE  = sm + 53008;
    float* shFB  = sm + 54096;
    float* shY   = sm + 55632;
    float* shTR  = sm + 56144;
    float* shTW  = sm + 56176;
    float* shFJ3 = shA + 8192;       // alias: live only layer3->epilogue

    const int tid = threadIdx.x;
    const int u = tid % 96;          // column-pair index
    const int g = tid / 96;          // sample octet (0..3)
    const int wid = tid >> 5;        // warp id (uniform g per warp: 3 warps/group)
    const int lane = tid & 31;
    const int j0 = 2 * u;
    const int sb = 8 * g;            // sample base within tile
    const int s0 = blockIdx.x * TM;
    const float dtf = -0.1f;

    // per-thread constants (register-resident)
    const float2 w1tReg = *(const float2*)(W1 + 272 * 192 + j0);
    const float2 b2Reg  = *(const float2*)(b2 + j0);

    // ---------------- phase 0: stage weights / state ----------------
    {
        const float4* W2g4 = (const float4*)W2;
        float4* shW24 = (float4*)shW2;
        for (int i = tid; i < 36864 / 4; i += NTHR) shW24[i] = W2g4[i];
        for (int i = tid; i < 3072; i += NTHR) {                           // W3 transpose
            int k = i >> 4, dd = i & 15;
            shW3t[dd * 192 + k] = W3[i];
        }
        if (tid < 16) shB3[tid] = b3[tid];
        if (tid < 32) shTR[tid] = 0.f;
        for (int i = tid; i < 512; i += NTHR) shY[i] = theta[s0 * 16 + i];
        // h tile into shA as hS[c][s], row stride 32 (prologue only)
        const float4* hg4 = (const float4*)hg;
        for (int i = tid; i < 2048; i += NTHR) {
            float4 v = hg4[s0 * 64 + i];
            int s = i >> 6, c = (i & 63) * 4;
            shA[(c + 0) * 32 + s] = v.x; shA[(c + 1) * 32 + s] = v.y;
            shA[(c + 2) * 32 + s] = v.z; shA[(c + 3) * 32 + s] = v.w;
        }
    }
    __syncthreads();

    // ------------- hc = b1 + h @ W1[16:272,:] (register resident) -------------
    u64 hcReg[2][4];
    {
        float2 bj = *(const float2*)(b1 + j0);
        #pragma unroll
        for (int p = 0; p < 4; p++) { hcReg[0][p] = pk2(bj.x, bj.x); hcReg[1][p] = pk2(bj.y, bj.y); }
        const float* hrow = shA + sb;
        #pragma unroll 4
        for (int k = 0; k < 256; k++) {
            float2 w = *(const float2*)(W1 + (16 + k) * 192 + j0);         // L2-resident LDG
            u64 w0 = pk2(w.x, w.x), w1 = pk2(w.y, w.y);
            const ulonglong2* ap = (const ulonglong2*)(hrow + k * 32);
            ulonglong2 A0 = ap[0], A1 = ap[1];
            fma2(hcReg[0][0], A0.x, w0); fma2(hcReg[0][1], A0.y, w0);
            fma2(hcReg[0][2], A1.x, w0); fma2(hcReg[0][3], A1.y, w0);
            fma2(hcReg[1][0], A0.x, w1); fma2(hcReg[1][1], A0.y, w1);
            fma2(hcReg[1][2], A1.x, w1); fma2(hcReg[1][3], A1.y, w1);
        }
    }
    __syncthreads();   // hS dead; shA free for act rows

    const float kSQ = 0.70710678118654752f;    // 1/sqrt(2)
    const float kPDF = 0.3989422804014327f;    // 1/sqrt(2*pi)

    u64 aA[2][4], aD[2][4], aW[2][4];

    // eps prefetch: 512 slots over 384 threads (2nd slot: tid<128)
    float epsReg[2];
    epsReg[0] = eps[(0 * B_TOT + s0 + (tid >> 4)) * 16 + (tid & 15)];
    epsReg[1] = (tid < 128)
        ? eps[(0 * B_TOT + s0 + ((tid + 384) >> 4)) * 16 + ((tid + 384) & 15)] : 0.f;

    for (int step = 0; step < NSTEPS_; step++) {
        float t0 = 1.0f + dtf * (float)step;
        for (int st = 0; st < 4; st++) {
            int idx = step * 4 + st;
            float tc = t0 + dtf * (st == 0 ? 0.f : st == 1 ? (1.f / 3.f)
                                 : st == 2 ? (2.f / 3.f) : 1.f);

            // ---- phase A: stage y + eps into shYE ----
            #pragma unroll
            for (int r = 0; r < 2; r++) {
                int i = tid + r * 384;
                if (r == 0 || tid < 128) {
                    int s = i >> 4, d = i & 15;
                    shYE[d * 68 + 32 + s] = epsReg[r];
                    float yb = shY[i];
                    float yc;
                    if      (st == 0) yc = yb;
                    else if (st == 1) yc = yb + (dtf * (1.f / 3.f)) * shFB[i];
                    else if (st == 2) yc = yb + dtf * (shFB[512 + i] - (1.f / 3.f) * shFB[i]);
                    else              yc = yb + dtf * (shFB[i] - shFB[512 + i] + shFB[1024 + i]);
                    shYE[d * 68 + s] = yc;
                    int nxt = idx + 1; if (nxt > 39) nxt = 39;
                    epsReg[r] = eps[(nxt * B_TOT + s0 + s) * 16 + d];      // prefetch
                }
            }
            __syncthreads();

            // ---- layer 1: z1 = hc + t*W1t + y@W1a ; dz1 = e@W1a ; we = W3.e ----
            {
                u64 tw0 = pk2(tc * w1tReg.x, tc * w1tReg.x);
                u64 tw1 = pk2(tc * w1tReg.y, tc * w1tReg.y);
                #pragma unroll
                for (int p = 0; p < 4; p++) {
                    aA[0][p] = hcReg[0][p]; add2(aA[0][p], tw0);
                    aA[1][p] = hcReg[1][p]; add2(aA[1][p], tw1);
                    aD[0][p] = aD[1][p] = 0ull;
                    aW[0][p] = aW[1][p] = 0ull;
                }
            }
            #pragma unroll
            for (int k = 0; k < 16; k++) {
                const float* ar = shYE + k * 68 + sb;
                ulonglong2 A0 = *(const ulonglong2*)ar;
                ulonglong2 A1 = *(const ulonglong2*)(ar + 4);
                ulonglong2 E0 = *(const ulonglong2*)(ar + 32);
                ulonglong2 E1 = *(const ulonglong2*)(ar + 36);
                float2 w  = *(const float2*)(W1 + k * 192 + j0);           // L1-resident LDG
                float2 w3 = *(const float2*)(shW3t + k * 192 + j0);
                u64 w0 = pk2(w.x, w.x), w1 = pk2(w.y, w.y);
                u64 v0 = pk2(w3.x, w3.x), v1 = pk2(w3.y, w3.y);
                fma2(aA[0][0], A0.x, w0); fma2(aA[0][1], A0.y, w0);
                fma2(aA[0][2], A1.x, w0); fma2(aA[0][3], A1.y, w0);
                fma2(aA[1][0], A0.x, w1); fma2(aA[1][1], A0.y, w1);
                fma2(aA[1][2], A1.x, w1); fma2(aA[1][3], A1.y, w1);
                fma2(aD[0][0], E0.x, w0); fma2(aD[0][1], E0.y, w0);
                fma2(aD[0][2], E1.x, w0); fma2(aD[0][3], E1.y, w0);
                fma2(aD[1][0], E0.x, w1); fma2(aD[1][1], E0.y, w1);
                fma2(aD[1][2], E1.x, w1); fma2(aD[1][3], E1.y, w1);
                fma2(aW[0][0], E0.x, v0); fma2(aW[0][1], E0.y, v0);
                fma2(aW[0][2], E1.x, v0); fma2(aW[0][3], E1.y, v0);
                fma2(aW[1][0], E0.x, v1); fma2(aW[1][1], E0.y, v1);
                fma2(aW[1][2], E1.x, v1); fma2(aW[1][3], E1.y, v1);
            }

            // GELU layer1 + store a1/d1 rows [a32|d32]
            #pragma unroll
            for (int jj = 0; jj < 2; jj++) {
                float va[8], vd[8];
                #pragma unroll
                for (int p = 0; p < 4; p++) {
                    float2 z  = upk2(aA[jj][p]);
                    float2 dz = upk2(aD[jj][p]);
                    float c0 = 0.5f * (1.f + erff(z.x * kSQ));
                    float c1 = 0.5f * (1.f + erff(z.y * kSQ));
                    va[2 * p]     = z.x * c0;
                    va[2 * p + 1] = z.y * c1;
                    float g0 = c0 + z.x * kPDF * __expf(-0.5f * z.x * z.x);
                    float g1 = c1 + z.y * kPDF * __expf(-0.5f * z.y * z.y);
                    vd[2 * p]     = g0 * dz.x;
                    vd[2 * p + 1] = g1 * dz.y;
                }
                float* row = shA + (j0 + jj) * 68 + sb;
                *(float4*)(row)      = make_float4(va[0], va[1], va[2], va[3]);
                *(float4*)(row + 4)  = make_float4(va[4], va[5], va[6], va[7]);
                *(float4*)(row + 32) = make_float4(vd[0], vd[1], vd[2], vd[3]);
                *(float4*)(row + 36) = make_float4(vd[4], vd[5], vd[6], vd[7]);
            }
            __syncthreads();

            // ---- layer 2: z2 = a1@W2 + b2 ; dz2 = d1@W2 ----
            #pragma unroll
            for (int p = 0; p < 4; p++) {
                aA[0][p] = pk2(b2Reg.x, b2Reg.x);
                aA[1][p] = pk2(b2Reg.y, b2Reg.y);
                aD[0][p] = aD[1][p] = 0ull;
            }
            #pragma unroll 6
            for (int k = 0; k < 192; k++) {
                const float* ar = shA + k * 68 + sb;
                ulonglong2 A0 = *(const ulonglong2*)ar;
                ulonglong2 A1 = *(const ulonglong2*)(ar + 4);
                ulonglong2 E0 = *(const ulonglong2*)(ar + 32);
                ulonglong2 E1 = *(const ulonglong2*)(ar + 36);
                float2 w = *(const float2*)(shW2 + k * 192 + j0);
                u64 w0 = pk2(w.x, w.x), w1 = pk2(w.y, w.y);
                fma2(aA[0][0], A0.x, w0); fma2(aA[0][1], A0.y, w0);
                fma2(aA[0][2], A1.x, w0); fma2(aA[0][3], A1.y, w0);
                fma2(aA[1][0], A0.x, w1); fma2(aA[1][1], A0.y, w1);
                fma2(aA[1][2], A1.x, w1); fma2(aA[1][3], A1.y, w1);
                fma2(aD[0][0], E0.x, w0); fma2(aD[0][1], E0.y, w0);
                fma2(aD[0][2], E1.x, w0); fma2(aD[0][3], E1.y, w0);
                fma2(aD[1][0], E0.x, w1); fma2(aD[1][1], E0.y, w1);
                fma2(aD[1][2], E1.x, w1); fma2(aD[1][3], E1.y, w1);
            }
            __syncthreads();   // act rows dead; shA front reused as a2t

            // GELU layer2: store a2 transposed (stride 196); trace partial in regs
            float tp[8];
            #pragma unroll
            for (int i = 0; i < 8; i++) tp[i] = 0.f;
            #pragma unroll
            for (int jj = 0; jj < 2; jj++) {
                #pragma unroll
                for (int p = 0; p < 4; p++) {
                    float2 z  = upk2(aA[jj][p]);
                    float2 dz = upk2(aD[jj][p]);
                    float c0 = 0.5f * (1.f + erff(z.x * kSQ));
                    float c1 = 0.5f * (1.f + erff(z.y * kSQ));
                    float a0 = z.x * c0, a1v = z.y * c1;
                    float g0 = c0 + z.x * kPDF * __expf(-0.5f * z.x * z.x);
                    float g1 = c1 + z.y * kPDF * __expf(-0.5f * z.y * z.y);
                    float d0 = g0 * dz.x, d1v = g1 * dz.y;
                    int ca = sb + 2 * p;
                    shA[(ca)     * 196 + j0 + jj] = a0;
                    shA[(ca + 1) * 196 + j0 + jj] = a1v;
                    float2 wv = upk2(aW[jj][p]);
                    tp[2 * p]     += d0  * wv.x;     // d2 . (W3 e)
                    tp[2 * p + 1] += d1v * wv.y;
                }
            }
            // warp butterfly reduce (warp uniform in g)
            #pragma unroll
            for (int off = 16; off > 0; off >>= 1) {
                #pragma unroll
                for (int i = 0; i < 8; i++)
                    tp[i] += __shfl_xor_sync(0xFFFFFFFFu, tp[i], off);
            }
            if (lane == 0) {
                #pragma unroll
                for (int i = 0; i < 8; i++) shTW[wid * 8 + i] = tp[i];
            }
            __syncthreads();

            // ---- layer 3 (a-path): f = a2 @ W3, 3-way K-split, 1536 microtasks ----
            #pragma unroll
            for (int r = 0; r < 4; r++) {
                int m = tid + 384 * r;
                int third = m >> 9, o = m & 511;
                int s = o & 31, dd = o >> 5;
                const float* ap = shA + s * 196 + third * 64;
                const float* wp = shW3t + dd * 192 + third * 64;
                float acc = 0.f;
                #pragma unroll 8
                for (int k = 0; k < 64; k += 4) {
                    float4 av = *(const float4*)(ap + k);
                    float4 wv = *(const float4*)(wp + k);
                    acc += av.x * wv.x + av.y * wv.y + av.z * wv.z + av.w * wv.w;
                }
                shFJ3[third * 544 + s * 17 + dd] = acc;
            }
            __syncthreads();

            // ---- epilogue: f store / RK4 combine / trace accumulate ----
            float wst = (st == 1 || st == 2) ? 3.f : 1.f;
            for (int i = tid; i < 512; i += NTHR) {
                int s = i >> 4, d = i & 15;
                float f = shFJ3[s * 17 + d] + shFJ3[544 + s * 17 + d]
                        + shFJ3[1088 + s * 17 + d] + shB3[d];
                if (st < 3) shFB[st * 512 + i] = f;
                else shY[i] += dtf * 0.125f *
                     (shFB[i] + 3.f * (shFB[512 + i] + shFB[1024 + i]) + f);
            }
            if (tid < 32) {
                int s = tid;
                int gq = s >> 3, si = s & 7;
                float tr = shTW[(3 * gq) * 8 + si] + shTW[(3 * gq + 1) * 8 + si]
                         + shTW[(3 * gq + 2) * 8 + si];
                shTR[s] += wst * tr;
            }
            __syncthreads();
        }
    }

    // logp = -0.5*||z0||^2 - 8*log(2pi) - dlogp ;  dlogp = -dt/8 * sum(w*tr)
    if (tid < 32) {
        int s = tid;
        float ss = 0.f;
        #pragma unroll
        for (int d = 0; d < 16; d++) { float v = shY[s * 16 + d]; ss += v * v; }
        out[s0 + s] = -0.5f * ss - 14.703016531274763f + dtf * 0.125f * shTR[s];
    }
}

extern "C" void kernel_launch(void* const* d_in, const int* in_sizes, int n_in,
                              void* d_out, int out_size) {
    const float* theta = (const float*)d_in[0];
    const float* hg    = (const float*)d_in[1];
    const float* eps   = (const float*)d_in[2];
    const float* W1    = (const float*)d_in[3];
    const float* b1    = (const float*)d_in[4];
    const float* W2    = (const float*)d_in[5];
    const float* b2    = (const float*)d_in[6];
    const float* W3    = (const float*)d_in[7];
    const float* b3    = (const float*)d_in[8];
    float* out = (float*)d_out;

    cudaFuncSetAttribute(ConditionalCNF_27590869910221_kernel,
                         cudaFuncAttributeMaxDynamicSharedMemorySize,
                         SMEM_FLOATS * (int)sizeof(float));
    ConditionalCNF_27590869910221_kernel<<<B_TOT / TM, NTHR,
                                           SMEM_FLOATS * sizeof(float)>>>(
        theta, hg, eps, W1, b1, W2, b2, W3, b3, out);
}

// round 12
// speedup vs baseline: 1.5935x; 1.5935x over previous
#include <cuda_runtime.h>

#define B_TOT   16384
#define TM      16
#define NTHR    384
#define NSTEPS_ 10

typedef unsigned long long u64;

__device__ __forceinline__ u64 pk2(float lo, float hi) {
    u64 r; asm("mov.b64 %0,{%1,%2};" : "=l"(r) : "f"(lo), "f"(hi)); return r;
}
__device__ __forceinline__ float2 upk2(u64 v) {
    float2 f; asm("mov.b64 {%0,%1},%2;" : "=f"(f.x), "=f"(f.y) : "l"(v)); return f;
}
__device__ __forceinline__ void fma2(u64& d, u64 a, u64 b) {
    asm("fma.rn.f32x2 %0,%1,%2,%0;" : "+l"(d) : "l"(a), "l"(b));
}
__device__ __forceinline__ void add2(u64& d, u64 a) {
    asm("add.rn.f32x2 %0,%0,%1;" : "+l"(d) : "l"(a));
}

// Shared layout (floats):
//   [0,36864)      shW2   192x192
//   [36864,43776)  shAct  192x36  act rows [a16|d16|pad4]  (hS 256x16 in prologue)
//   [43776,46912)  shA2t  16x196  transposed a2 (own region -> no WAR barrier)
//   [46912,49984)  shW1a  16x192
//   [49984,53056)  shW3t  16x192
//   [53056,53072)  shB3   16
//   [53072,53648)  shYE   16x36  [y16|e16|pad4]
//   [53648,54464)  shFJ3  3x(16x17)
//   [54464,54560)  shTW   12x4 warp trace partials (+pad)
//   [54560,54576)  shTR   16
#define SMEM_FLOATS 54576

__global__ __launch_bounds__(NTHR, 1)
void ConditionalCNF_27590869910221_kernel(
    const float* __restrict__ theta, const float* __restrict__ hg,
    const float* __restrict__ eps,   const float* __restrict__ W1,
    const float* __restrict__ b1,    const float* __restrict__ W2,
    const float* __restrict__ b2,    const float* __restrict__ W3,
    const float* __restrict__ b3,    float* __restrict__ out)
{
    extern __shared__ float sm[];
    float* shW2  = sm;
    float* shAct = sm + 36864;
    float* shA2t = sm + 43776;
    float* shW1a = sm + 46912;
    float* shW3t = sm + 49984;
    float* shB3  = sm + 53056;
    float* shYE  = sm + 53072;
    float* shFJ3 = sm + 53648;
    float* shTW  = sm + 54464;
    float* shTR  = sm + 54560;

    const int tid = threadIdx.x;
    const int u = tid % 96;          // column-pair index
    const int g = tid / 96;          // sample quartet (0..3)
    const int wid = tid >> 5;        // warp id (uniform g per warp: 3 warps/group)
    const int lane = tid & 31;
    const int j0 = 2 * u;
    const int sb = 4 * g;            // sample base within tile
    const int s0 = blockIdx.x * TM;
    const float dtf = -0.1f;
    const int es = tid >> 4, ed = tid & 15;   // slot (sample, dim) for tid<256

    // per-thread constants
    const float2 w1tReg = *(const float2*)(W1 + 272 * 192 + j0);
    const float2 b2Reg  = *(const float2*)(b2 + j0);

    // ---------------- phase 0: stage weights / state ----------------
    float yReg = 0.f, fb1 = 0.f, fb2 = 0.f, fb3 = 0.f, epsReg = 0.f;
    {
        const float4* W2g4 = (const float4*)W2;
        float4* shW24 = (float4*)shW2;
        for (int i = tid; i < 36864 / 4; i += NTHR) shW24[i] = W2g4[i];
        for (int i = tid; i < 3072; i += NTHR) shW1a[i] = W1[i];           // rows 0..15
        for (int i = tid; i < 3072; i += NTHR) {                           // W3 transpose
            int k = i >> 4, dd = i & 15;
            shW3t[dd * 192 + k] = W3[i];
        }
        if (tid < 16) { shB3[tid] = b3[tid]; shTR[tid] = 0.f; }
        if (tid < 256) {
            yReg = theta[s0 * 16 + tid];
            epsReg = eps[(0 * B_TOT + s0 + es) * 16 + ed];
        }
        // h tile into shAct as hS[c][s], row stride 16 (prologue alias)
        const float4* hg4 = (const float4*)hg;
        for (int i = tid; i < 1024; i += NTHR) {
            float4 v = hg4[s0 * 64 + i];
            int s = i >> 6, c = (i & 63) * 4;
            shAct[(c + 0) * 16 + s] = v.x; shAct[(c + 1) * 16 + s] = v.y;
            shAct[(c + 2) * 16 + s] = v.z; shAct[(c + 3) * 16 + s] = v.w;
        }
    }
    __syncthreads();

    // ------------- hc = b1 + h @ W1[16:272,:] (register resident) -------------
    u64 hcReg[2][2];
    {
        float2 bj = *(const float2*)(b1 + j0);
        hcReg[0][0] = hcReg[0][1] = pk2(bj.x, bj.x);
        hcReg[1][0] = hcReg[1][1] = pk2(bj.y, bj.y);
        const float* hrow = shAct + sb;
        #pragma unroll 4
        for (int k = 0; k < 256; k++) {
            float2 w = *(const float2*)(W1 + (16 + k) * 192 + j0);         // L2-resident LDG
            u64 w0 = pk2(w.x, w.x), w1 = pk2(w.y, w.y);
            ulonglong2 A0 = *(const ulonglong2*)(hrow + k * 16);
            fma2(hcReg[0][0], A0.x, w0); fma2(hcReg[0][1], A0.y, w0);
            fma2(hcReg[1][0], A0.x, w1); fma2(hcReg[1][1], A0.y, w1);
        }
    }
    // shYE init for stage 0 (y = theta, eps[0]); prefetch eps[1]
    if (tid < 256) {
        shYE[ed * 36 + es] = yReg;
        shYE[ed * 36 + 16 + es] = epsReg;
        epsReg = eps[(1 * B_TOT + s0 + es) * 16 + ed];
    }
    __syncthreads();   // hS dead; shYE(0) ready

    const float kSQ = 0.70710678118654752f;    // 1/sqrt(2)
    const float kPDF = 0.3989422804014327f;    // 1/sqrt(2*pi)

    u64 aA[2][2], aD[2][2], aW[2][2];

    for (int idx = 0; idx < 40; idx++) {
        int st = idx & 3;
        float t0 = 1.0f + dtf * (float)(idx >> 2);
        float tc = t0 + dtf * (st == 0 ? 0.f : st == 1 ? (1.f / 3.f)
                             : st == 2 ? (2.f / 3.f) : 1.f);

        // ---- layer 1: z1 = hc + t*W1t + y@W1a ; dz1 = e@W1a ; we = W3.e ----
        {
            u64 tw0 = pk2(tc * w1tReg.x, tc * w1tReg.x);
            u64 tw1 = pk2(tc * w1tReg.y, tc * w1tReg.y);
            #pragma unroll
            for (int p = 0; p < 2; p++) {
                aA[0][p] = hcReg[0][p]; add2(aA[0][p], tw0);
                aA[1][p] = hcReg[1][p]; add2(aA[1][p], tw1);
                aD[0][p] = aD[1][p] = 0ull;
                aW[0][p] = aW[1][p] = 0ull;
            }
        }
        #pragma unroll
        for (int k = 0; k < 16; k++) {
            const float* ar = shYE + k * 36 + sb;
            ulonglong2 A0 = *(const ulonglong2*)ar;
            ulonglong2 E0 = *(const ulonglong2*)(ar + 16);
            float2 w  = *(const float2*)(shW1a + k * 192 + j0);
            float2 w3 = *(const float2*)(shW3t + k * 192 + j0);
            u64 w0 = pk2(w.x, w.x), w1 = pk2(w.y, w.y);
            u64 v0 = pk2(w3.x, w3.x), v1 = pk2(w3.y, w3.y);
            fma2(aA[0][0], A0.x, w0); fma2(aA[0][1], A0.y, w0);
            fma2(aA[1][0], A0.x, w1); fma2(aA[1][1], A0.y, w1);
            fma2(aD[0][0], E0.x, w0); fma2(aD[0][1], E0.y, w0);
            fma2(aD[1][0], E0.x, w1); fma2(aD[1][1], E0.y, w1);
            fma2(aW[0][0], E0.x, v0); fma2(aW[0][1], E0.y, v0);
            fma2(aW[1][0], E0.x, v1); fma2(aW[1][1], E0.y, v1);
        }

        // GELU layer1 + store a1/d1 rows [a16|d16]
        #pragma unroll
        for (int jj = 0; jj < 2; jj++) {
            float va[4], vd[4];
            #pragma unroll
            for (int p = 0; p < 2; p++) {
                float2 z  = upk2(aA[jj][p]);
                float2 dz = upk2(aD[jj][p]);
                float c0 = 0.5f * (1.f + erff(z.x * kSQ));
                float c1 = 0.5f * (1.f + erff(z.y * kSQ));
                va[2 * p]     = z.x * c0;
                va[2 * p + 1] = z.y * c1;
                float g0 = c0 + z.x * kPDF * __expf(-0.5f * z.x * z.x);
                float g1 = c1 + z.y * kPDF * __expf(-0.5f * z.y * z.y);
                vd[2 * p]     = g0 * dz.x;
                vd[2 * p + 1] = g1 * dz.y;
            }
            float* row = shAct + (j0 + jj) * 36 + sb;
            *(float4*)(row)      = make_float4(va[0], va[1], va[2], va[3]);
            *(float4*)(row + 16) = make_float4(vd[0], vd[1], vd[2], vd[3]);
        }
        __syncthreads();   // B: act rows ready

        // ---- layer 2: z2 = a1@W2 + b2 ; dz2 = d1@W2 ----
        #pragma unroll
        for (int p = 0; p < 2; p++) {
            aA[0][p] = pk2(b2Reg.x, b2Reg.x);
            aA[1][p] = pk2(b2Reg.y, b2Reg.y);
            aD[0][p] = aD[1][p] = 0ull;
        }
        #pragma unroll 8
        for (int k = 0; k < 192; k++) {
            const float* ar = shAct + k * 36 + sb;
            ulonglong2 A0 = *(const ulonglong2*)ar;
            ulonglong2 E0 = *(const ulonglong2*)(ar + 16);
            float2 w = *(const float2*)(shW2 + k * 192 + j0);
            u64 w0 = pk2(w.x, w.x), w1 = pk2(w.y, w.y);
            fma2(aA[0][0], A0.x, w0); fma2(aA[0][1], A0.y, w0);
            fma2(aA[1][0], A0.x, w1); fma2(aA[1][1], A0.y, w1);
            fma2(aD[0][0], E0.x, w0); fma2(aD[0][1], E0.y, w0);
            fma2(aD[1][0], E0.x, w1); fma2(aD[1][1], E0.y, w1);
        }

        // GELU layer2: a2 -> shA2t (own region, no barrier needed); trace in regs
        float tp[4] = {0.f, 0.f, 0.f, 0.f};
        #pragma unroll
        for (int jj = 0; jj < 2; jj++) {
            #pragma unroll
            for (int p = 0; p < 2; p++) {
                float2 z  = upk2(aA[jj][p]);
                float2 dz = upk2(aD[jj][p]);
                float c0 = 0.5f * (1.f + erff(z.x * kSQ));
                float c1 = 0.5f * (1.f + erff(z.y * kSQ));
                float a0 = z.x * c0, a1v = z.y * c1;
                float g0 = c0 + z.x * kPDF * __expf(-0.5f * z.x * z.x);
                float g1 = c1 + z.y * kPDF * __expf(-0.5f * z.y * z.y);
                float d0 = g0 * dz.x, d1v = g1 * dz.y;
                int ca = sb + 2 * p;
                shA2t[(ca)     * 196 + j0 + jj] = a0;
                shA2t[(ca + 1) * 196 + j0 + jj] = a1v;
                float2 wv = upk2(aW[jj][p]);
                tp[2 * p]     += d0  * wv.x;     // d2 . (W3 e)
                tp[2 * p + 1] += d1v * wv.y;
            }
        }
        // warp butterfly reduce (warp uniform in g)
        #pragma unroll
        for (int off = 16; off > 0; off >>= 1) {
            #pragma unroll
            for (int i = 0; i < 4; i++)
                tp[i] += __shfl_xor_sync(0xFFFFFFFFu, tp[i], off);
        }
        if (lane == 0) {
            #pragma unroll
            for (int i = 0; i < 4; i++) shTW[wid * 4 + i] = tp[i];
        }
        __syncthreads();   // D: a2t + shTW ready (also closes layer2 act reads)

        // ---- layer 3: f = a2 @ W3, 3-way K-split, 768 microtasks over 384 thr ----
        #pragma unroll
        for (int r = 0; r < 2; r++) {
            int m = tid + 384 * r;
            int third = m >> 8, o = m & 255;
            int s = o & 15, dd = o >> 4;
            const float* ap = shA2t + s * 196 + third * 64;
            const float* wp = shW3t + dd * 192 + third * 64;
            float acc = 0.f;
            #pragma unroll 8
            for (int k = 0; k < 64; k += 4) {
                float4 av = *(const float4*)(ap + k);
                float4 wv = *(const float4*)(wp + k);
                acc += av.x * wv.x + av.y * wv.y + av.z * wv.z + av.w * wv.w;
            }
            shFJ3[third * 272 + s * 17 + dd] = acc;
        }
        __syncthreads();   // E: shFJ3 ready

        // ---- fused epilogue + next-stage staging ----
        if (tid < 256) {
            float f = shFJ3[es * 17 + ed] + shFJ3[272 + es * 17 + ed]
                    + shFJ3[544 + es * 17 + ed] + shB3[ed];
            float yc;
            if      (st == 0) { fb1 = f; yc = yReg + (dtf * (1.f / 3.f)) * fb1; }
            else if (st == 1) { fb2 = f; yc = yReg + dtf * (fb2 - (1.f / 3.f) * fb1); }
            else if (st == 2) { fb3 = f; yc = yReg + dtf * (fb1 - fb2 + fb3); }
            else { yReg += dtf * 0.125f * (fb1 + 3.f * (fb2 + fb3) + f); yc = yReg; }
            if (idx < 39) {
                shYE[ed * 36 + es] = yc;
                shYE[ed * 36 + 16 + es] = epsReg;       // eps for stage idx+1
                int nxt = idx + 2; if (nxt > 39) nxt = 39;
                epsReg = eps[(nxt * B_TOT + s0 + es) * 16 + ed];
            }
        }
        if (tid < 16) {
            float wst = (st == 1 || st == 2) ? 3.f : 1.f;
            int gq = tid >> 2, si = tid & 3;
            float tr = shTW[(3 * gq) * 4 + si] + shTW[(3 * gq + 1) * 4 + si]
                     + shTW[(3 * gq + 2) * 4 + si];
            shTR[tid] += wst * tr;
        }
        __syncthreads();   // A: shYE(idx+1) ready
    }

    // gather y (register-resident, distributed over d-threads) then reduce
    if (tid < 256) shYE[es * 36 + ed] = yReg;
    __syncthreads();
    if (tid < 16) {
        float ss = 0.f;
        #pragma unroll
        for (int d = 0; d < 16; d++) { float v = shYE[tid * 36 + d]; ss += v * v; }
        out[s0 + tid] = -0.5f * ss - 14.703016531274763f + dtf * 0.125f * shTR[tid];
    }
}

extern "C" void kernel_launch(void* const* d_in, const int* in_sizes, int n_in,
                              void* d_out, int out_size) {
    const float* theta = (const float*)d_in[0];
    const float* hg    = (const float*)d_in[1];
    const float* eps   = (const float*)d_in[2];
    const float* W1    = (const float*)d_in[3];
    const float* b1    = (const float*)d_in[4];
    const float* W2    = (const float*)d_in[5];
    const float* b2    = (const float*)d_in[6];
    const float* W3    = (const float*)d_in[7];
    const float* b3    = (const float*)d_in[8];
    float* out = (float*)d_out;

    cudaFuncSetAttribute(ConditionalCNF_27590869910221_kernel,
                         cudaFuncAttributeMaxDynamicSharedMemorySize,
                         SMEM_FLOATS * (int)sizeof(float));
    ConditionalCNF_27590869910221_kernel<<<B_TOT / TM, NTHR,
                                           SMEM_FLOATS * sizeof(float)>>>(
        theta, hg, eps, W1, b1, W2, b2, W3, b3, out);
}